// round 3
// baseline (speedup 1.0000x reference)
#include <cuda_runtime.h>
#include <cstdint>
#include <cfloat>

// Problem constants
#define N_PIX   16777216          // 16 * 1 * 1024 * 1024
#define NF4     4194304           // N_PIX / 4
#define RED_B   1024              // reduction blocks
#define BINS    256
#define GRIDT   8
#define TILES   1024              // 16 images * 8 * 8
#define CLIPV   2560.0f           // max(int(40.0*16384//256),1)

// Scratch (device globals only — no allocations allowed)
__device__ float         g_pmin[RED_B];
__device__ float         g_pmax[RED_B];
__device__ double        g_psum[RED_B];
__device__ double        g_psq [RED_B];
__device__ float         g_AB[2];
__device__ unsigned char g_bidx[N_PIX];
__device__ float         g_lut[TILES * BINS];

// ---------------------------------------------------------------------------
// Kernel 1: partial min/max/sum/sumsq. 1024 blocks x 256 threads, 64 elems/thr.
// ---------------------------------------------------------------------------
__global__ void __launch_bounds__(256) k_reduce(const float4* __restrict__ x)
{
    int tid = threadIdx.x;
    int t   = blockIdx.x * 256 + tid;

    float mn =  FLT_MAX, mx = -FLT_MAX;
    float s = 0.0f, q = 0.0f;
#pragma unroll
    for (int i = 0; i < 16; i++) {
        float4 v = x[t + i * (RED_B * 256)];
        mn = fminf(mn, fminf(fminf(v.x, v.y), fminf(v.z, v.w)));
        mx = fmaxf(mx, fmaxf(fmaxf(v.x, v.y), fmaxf(v.z, v.w)));
        s += (v.x + v.y) + (v.z + v.w);
        q += (v.x * v.x + v.y * v.y) + (v.z * v.z + v.w * v.w);
    }

    __shared__ float  smn[256], smx[256];
    __shared__ double ss[256], sq[256];
    smn[tid] = mn; smx[tid] = mx;
    ss[tid] = (double)s; sq[tid] = (double)q;
    __syncthreads();
    for (int o = 128; o > 0; o >>= 1) {
        if (tid < o) {
            smn[tid] = fminf(smn[tid], smn[tid + o]);
            smx[tid] = fmaxf(smx[tid], smx[tid + o]);
            ss[tid] += ss[tid + o];
            sq[tid] += sq[tid + o];
        }
        __syncthreads();
    }
    if (tid == 0) {
        g_pmin[blockIdx.x] = smn[0];
        g_pmax[blockIdx.x] = smx[0];
        g_psum[blockIdx.x] = ss[0];
        g_psq [blockIdx.x] = sq[0];
    }
}

// ---------------------------------------------------------------------------
// Kernel 2: final reduce + affine constants (faithful fp64 replica of the
// reference's normalize -> standardize -> normalize chain, collapsed to x*A+B)
// ---------------------------------------------------------------------------
__global__ void __launch_bounds__(1024) k_finalize()
{
    int tid = threadIdx.x;
    __shared__ float  smn[1024], smx[1024];
    __shared__ double ss[1024], sq[1024];
    smn[tid] = g_pmin[tid]; smx[tid] = g_pmax[tid];
    ss[tid]  = g_psum[tid]; sq[tid]  = g_psq[tid];
    __syncthreads();
    for (int o = 512; o > 0; o >>= 1) {
        if (tid < o) {
            smn[tid] = fminf(smn[tid], smn[tid + o]);
            smx[tid] = fmaxf(smx[tid], smx[tid + o]);
            ss[tid] += ss[tid + o];
            sq[tid] += sq[tid + o];
        }
        __syncthreads();
    }
    if (tid == 0) {
        double mn = (double)smn[0];
        double mx = (double)smx[0];
        double span = mx - mn;
        const double N = (double)N_PIX;
        double S = ss[0], Q = sq[0];
        // mean/var of x1 = (x-mn)/span, ddof=1
        double meanx = S / N;
        double varx  = (Q - S * S / N) / (N - 1.0);
        double mean1 = (meanx - mn) / span;
        double std1  = sqrt(varx) / span;
        // z = (x1-mean1)/std1; min/max of x1 are exactly 0 and 1
        double zmin  = (0.0 - mean1) / std1;
        double zmax  = (1.0 - mean1) / std1;
        double zspan = zmax - zmin;
        // x2 = ((x1 - mean1)/std1 - zmin)/zspan  ==  A*x + B
        double A = 1.0 / (span * std1 * zspan);
        double B = (((0.0 - mn) / span - mean1) / std1 - zmin) / zspan;
        g_AB[0] = (float)A;
        g_AB[1] = (float)B;
    }
}

// ---------------------------------------------------------------------------
// Kernel 3: one block per 128x128 tile. Histogram (smem atomics) + bidx store,
// then clip -> scan -> residual -> LUT, all in-block.
// ---------------------------------------------------------------------------
__global__ void __launch_bounds__(256) k_hist(const float* __restrict__ x)
{
    __shared__ unsigned int h[BINS];
    __shared__ float        cs[BINS];

    int t   = blockIdx.x;          // tile id: ((bc*8)+ti)*8+tj
    int tid = threadIdx.x;
    h[tid] = 0;
    __syncthreads();

    float A = g_AB[0], B = g_AB[1];

    int bc = t >> 6;
    int ti = (t >> 3) & 7;
    int tj = t & 7;
    int row0 = ti * 128;
    int col0 = tj * 128;

    const float4* xp = (const float4*)(x + ((size_t)bc << 20));
    uchar4*       bp = (uchar4*)(g_bidx + ((size_t)bc << 20));

#pragma unroll
    for (int it = 0; it < 16; it++) {
        int row   = row0 + it * 8 + (tid >> 5);
        int cidx4 = (row << 8) + (col0 >> 2) + (tid & 31);  // float4 index in image
        float4 v  = xp[cidx4];
        int b0 = min(max((int)(fmaf(v.x, A, B) * 256.0f), 0), 255);
        int b1 = min(max((int)(fmaf(v.y, A, B) * 256.0f), 0), 255);
        int b2 = min(max((int)(fmaf(v.z, A, B) * 256.0f), 0), 255);
        int b3 = min(max((int)(fmaf(v.w, A, B) * 256.0f), 0), 255);
        atomicAdd(&h[b0], 1u);
        atomicAdd(&h[b1], 1u);
        atomicAdd(&h[b2], 1u);
        atomicAdd(&h[b3], 1u);
        bp[cidx4] = make_uchar4((unsigned char)b0, (unsigned char)b1,
                                (unsigned char)b2, (unsigned char)b3);
    }
    __syncthreads();

    // clip + inclusive scan (Hillis-Steele) over 256 bins
    float v = fminf((float)h[tid], CLIPV);
    cs[tid] = v;
    __syncthreads();
#pragma unroll
    for (int off = 1; off < BINS; off <<= 1) {
        float add = (tid >= off) ? cs[tid - off] : 0.0f;
        __syncthreads();
        cs[tid] += add;
        __syncthreads();
    }
    float total = cs[BINS - 1];
    float resid = (16384.0f - total) * (1.0f / 256.0f);
    // cumsum(hist + resid)[k] == cs[k] + (k+1)*resid
    float lv = (cs[tid] + (float)(tid + 1) * resid) * (255.0f / 16384.0f);
    lv = floorf(fminf(fmaxf(lv, 0.0f), 255.0f));
    g_lut[t * BINS + tid] = lv;
}

// ---------------------------------------------------------------------------
// Kernel 4: bilinear-interpolated LUT apply. One thread = 4 pixels (uchar4).
// ---------------------------------------------------------------------------
__global__ void __launch_bounds__(256) k_apply(float4* __restrict__ out)
{
    int g    = blockIdx.x * 256 + threadIdx.x;    // uchar4 index, 0..NF4-1
    int base = g << 2;
    int bc   = base >> 20;
    int off  = base & 1048575;
    int row  = off >> 10;
    int col  = off & 1023;

    uchar4 b4 = ((const uchar4*)g_bidx)[g];
    unsigned int bs[4] = { b4.x, b4.y, b4.z, b4.w };

    float gi = fminf(fmaxf((row + 0.5f) * (1.0f / 128.0f) - 0.5f, 0.0f), 7.0f);
    int   i0 = (int)gi;
    float wy = gi - (float)i0;
    int   i1 = min(i0 + 1, 7);

    const float* lb = g_lut + ((size_t)bc << 6) * BINS;   // bc*64 tiles
    float r[4];
#pragma unroll
    for (int p = 0; p < 4; p++) {
        float gj = fminf(fmaxf((col + p + 0.5f) * (1.0f / 128.0f) - 0.5f, 0.0f), 7.0f);
        int   j0 = (int)gj;
        float wx = gj - (float)j0;
        int   j1 = min(j0 + 1, 7);

        float v00 = lb[(((i0 << 3) + j0) << 8) + bs[p]];
        float v01 = lb[(((i0 << 3) + j1) << 8) + bs[p]];
        float v10 = lb[(((i1 << 3) + j0) << 8) + bs[p]];
        float v11 = lb[(((i1 << 3) + j1) << 8) + bs[p]];

        float top = (1.0f - wx) * v00 + wx * v01;
        float bot = (1.0f - wx) * v10 + wx * v11;
        r[p] = ((1.0f - wy) * top + wy * bot) * (1.0f / 255.0f);
    }
    out[g] = make_float4(r[0], r[1], r[2], r[3]);
}

// ---------------------------------------------------------------------------
// Tail: y is INT32 (jax default x64-disabled downcasts randint int64 -> int32).
// Expected tail = numeric float32 conversion of each y value.
// ---------------------------------------------------------------------------
__global__ void k_tail(const int* __restrict__ y, float* __restrict__ dst, int n)
{
    int i = threadIdx.x;
    if (i < n) dst[i] = (float)y[i];
}

extern "C" void kernel_launch(void* const* d_in, const int* in_sizes, int n_in,
                              void* d_out, int out_size)
{
    const float* x   = (const float*)d_in[0];
    float*       out = (float*)d_out;

    k_reduce  <<<RED_B, 256>>>((const float4*)x);
    k_finalize<<<1, 1024>>>();
    k_hist    <<<TILES, 256>>>(x);
    k_apply   <<<NF4 / 256, 256>>>((float4*)out);

    int tail = out_size - N_PIX;
    if (tail > 0 && n_in >= 2) {
        k_tail<<<1, 128>>>((const int*)d_in[1], out + N_PIX, tail);
    }
}

// round 4
// speedup vs baseline: 1.0240x; 1.0240x over previous
#include <cuda_runtime.h>
#include <cstdint>
#include <cfloat>

// Problem constants
#define N_PIX   16777216          // 16 * 1 * 1024 * 1024
#define NF4     4194304           // N_PIX / 4
#define RED_B   1024              // reduction blocks
#define BINS    256
#define TILES   1024              // 16 images * 8 * 8
#define CLIPV   2560.0f           // max(int(40.0*16384//256),1)

// Scratch (device globals only — no allocations allowed)
__device__ float         g_pmin[RED_B];
__device__ float         g_pmax[RED_B];
__device__ double        g_psum[RED_B];
__device__ double        g_psq [RED_B];
__device__ float         g_AB[2];
__device__ unsigned char g_bidx[N_PIX];
__device__ float         g_lut[TILES * BINS];

// ---------------------------------------------------------------------------
// Kernel 1: partial min/max/sum/sumsq. 1024 blocks x 256 threads, 64 elems/thr.
// ---------------------------------------------------------------------------
__global__ void __launch_bounds__(256) k_reduce(const float4* __restrict__ x)
{
    int tid = threadIdx.x;
    int t   = blockIdx.x * 256 + tid;

    float mn =  FLT_MAX, mx = -FLT_MAX;
    float s = 0.0f, q = 0.0f;
#pragma unroll
    for (int i = 0; i < 16; i++) {
        float4 v = x[t + i * (RED_B * 256)];
        mn = fminf(mn, fminf(fminf(v.x, v.y), fminf(v.z, v.w)));
        mx = fmaxf(mx, fmaxf(fmaxf(v.x, v.y), fmaxf(v.z, v.w)));
        s += (v.x + v.y) + (v.z + v.w);
        q += (v.x * v.x + v.y * v.y) + (v.z * v.z + v.w * v.w);
    }

    __shared__ float  smn[256], smx[256];
    __shared__ double ss[256], sq[256];
    smn[tid] = mn; smx[tid] = mx;
    ss[tid] = (double)s; sq[tid] = (double)q;
    __syncthreads();
    for (int o = 128; o > 0; o >>= 1) {
        if (tid < o) {
            smn[tid] = fminf(smn[tid], smn[tid + o]);
            smx[tid] = fmaxf(smx[tid], smx[tid + o]);
            ss[tid] += ss[tid + o];
            sq[tid] += sq[tid + o];
        }
        __syncthreads();
    }
    if (tid == 0) {
        g_pmin[blockIdx.x] = smn[0];
        g_pmax[blockIdx.x] = smx[0];
        g_psum[blockIdx.x] = ss[0];
        g_psq [blockIdx.x] = sq[0];
    }
}

// ---------------------------------------------------------------------------
// Kernel 2: final reduce + affine constants (fp64 replica of the reference's
// normalize -> standardize -> normalize chain, collapsed to x*A+B)
// ---------------------------------------------------------------------------
__global__ void __launch_bounds__(1024) k_finalize()
{
    int tid = threadIdx.x;
    __shared__ float  smn[1024], smx[1024];
    __shared__ double ss[1024], sq[1024];
    smn[tid] = g_pmin[tid]; smx[tid] = g_pmax[tid];
    ss[tid]  = g_psum[tid]; sq[tid]  = g_psq[tid];
    __syncthreads();
    for (int o = 512; o > 0; o >>= 1) {
        if (tid < o) {
            smn[tid] = fminf(smn[tid], smn[tid + o]);
            smx[tid] = fmaxf(smx[tid], smx[tid + o]);
            ss[tid] += ss[tid + o];
            sq[tid] += sq[tid + o];
        }
        __syncthreads();
    }
    if (tid == 0) {
        double mn = (double)smn[0];
        double mx = (double)smx[0];
        double span = mx - mn;
        const double N = (double)N_PIX;
        double S = ss[0], Q = sq[0];
        double meanx = S / N;
        double varx  = (Q - S * S / N) / (N - 1.0);
        double mean1 = (meanx - mn) / span;
        double std1  = sqrt(varx) / span;
        double zmin  = (0.0 - mean1) / std1;
        double zmax  = (1.0 - mean1) / std1;
        double zspan = zmax - zmin;
        double A = 1.0 / (span * std1 * zspan);
        double B = (((0.0 - mn) / span - mean1) / std1 - zmin) / zspan;
        g_AB[0] = (float)A;
        g_AB[1] = (float)B;
    }
}

// ---------------------------------------------------------------------------
// Kernel 3: one block per 128x128 tile. Histogram with 4-way sub-histograms
// (quarters same-bin atomic serialization) + bidx store, then clip -> scan ->
// residual -> LUT, all in-block.
// ---------------------------------------------------------------------------
__global__ void __launch_bounds__(256) k_hist(const float* __restrict__ x)
{
    __shared__ unsigned int h[4][BINS];
    __shared__ float        cs[BINS];

    int t   = blockIdx.x;          // tile id: ((bc*8)+ti)*8+tj
    int tid = threadIdx.x;
#pragma unroll
    for (int k = 0; k < 4; k++) h[k][tid] = 0;
    __syncthreads();

    float A = g_AB[0], B = g_AB[1];

    int bc = t >> 6;
    int ti = (t >> 3) & 7;
    int tj = t & 7;
    int row0 = ti * 128;
    int col0 = tj * 128;
    int wsub = (tid >> 5) & 3;     // warp -> sub-histogram

    const float4* xp = (const float4*)(x + ((size_t)bc << 20));
    uchar4*       bp = (uchar4*)(g_bidx + ((size_t)bc << 20));

#pragma unroll
    for (int it = 0; it < 16; it++) {
        int row   = row0 + it * 8 + (tid >> 5);
        int cidx4 = (row << 8) + (col0 >> 2) + (tid & 31);  // float4 index in image
        float4 v  = xp[cidx4];
        int b0 = min(max((int)(fmaf(v.x, A, B) * 256.0f), 0), 255);
        int b1 = min(max((int)(fmaf(v.y, A, B) * 256.0f), 0), 255);
        int b2 = min(max((int)(fmaf(v.z, A, B) * 256.0f), 0), 255);
        int b3 = min(max((int)(fmaf(v.w, A, B) * 256.0f), 0), 255);
        atomicAdd(&h[wsub][b0], 1u);
        atomicAdd(&h[wsub][b1], 1u);
        atomicAdd(&h[wsub][b2], 1u);
        atomicAdd(&h[wsub][b3], 1u);
        bp[cidx4] = make_uchar4((unsigned char)b0, (unsigned char)b1,
                                (unsigned char)b2, (unsigned char)b3);
    }
    __syncthreads();

    // clip + inclusive scan (Hillis-Steele) over 256 bins
    float v = fminf((float)(h[0][tid] + h[1][tid] + h[2][tid] + h[3][tid]), CLIPV);
    cs[tid] = v;
    __syncthreads();
#pragma unroll
    for (int off = 1; off < BINS; off <<= 1) {
        float add = (tid >= off) ? cs[tid - off] : 0.0f;
        __syncthreads();
        cs[tid] += add;
        __syncthreads();
    }
    float total = cs[BINS - 1];
    float resid = (16384.0f - total) * (1.0f / 256.0f);
    float lv = (cs[tid] + (float)(tid + 1) * resid) * (255.0f / 16384.0f);
    lv = floorf(fminf(fmaxf(lv, 0.0f), 255.0f));
    g_lut[t * BINS + tid] = lv;
}

// ---------------------------------------------------------------------------
// Kernel 4: bilinear LUT apply with shared-memory staged LUT.
// One block per (image, 64-row band): within a band i0/i1 are CONSTANT, so we
// stage the two needed LUT rows interleaved as float2[8*256] (16 KB) and each
// pixel does 2x LDS.64 instead of 4 divergent global gathers.
// ---------------------------------------------------------------------------
__global__ void __launch_bounds__(1024) k_apply(float4* __restrict__ out)
{
    __shared__ float2 slut[8 * BINS];   // (j, bin) -> (lut[i0], lut[i1])

    int blk  = blockIdx.x;       // 0..255
    int bc   = blk >> 4;         // image
    int band = blk & 15;         // 64-row band index
    int i0   = (band == 0) ? 0 : ((band - 1) >> 1);
    int i1   = min(i0 + 1, 7);

    const float* lb = g_lut + ((size_t)bc << 6) * BINS;  // this image's 64 tiles
#pragma unroll
    for (int s = threadIdx.x; s < 8 * BINS; s += 1024) {
        int j = s >> 8, b = s & 255;
        slut[s] = make_float2(lb[(((i0 << 3) + j) << 8) + b],
                              lb[(((i1 << 3) + j) << 8) + b]);
    }
    __syncthreads();

    int base_f4 = (bc << 18) + (band << 14);   // float4 index of band start
    const uchar4* bp = (const uchar4*)g_bidx;

#pragma unroll
    for (int it = 0; it < 16; it++) {
        int idx  = (it << 10) + threadIdx.x;   // 0..16383 within band
        int rowb = idx >> 8;                   // 0..63
        int col4 = idx & 255;
        int g    = base_f4 + idx;

        uchar4 b4 = bp[g];
        unsigned int bs[4] = { b4.x, b4.y, b4.z, b4.w };

        int   row = (band << 6) + rowb;
        float gi  = fminf(fmaxf((row + 0.5f) * (1.0f / 128.0f) - 0.5f, 0.0f), 7.0f);
        float wy  = gi - (float)i0;

        float r[4];
#pragma unroll
        for (int p = 0; p < 4; p++) {
            int   col = (col4 << 2) + p;
            float gj  = fminf(fmaxf((col + 0.5f) * (1.0f / 128.0f) - 0.5f, 0.0f), 7.0f);
            int   j0  = (int)gj;
            float wx  = gj - (float)j0;
            int   j1  = min(j0 + 1, 7);

            float2 a = slut[(j0 << 8) + bs[p]];   // (v00, v10)
            float2 c = slut[(j1 << 8) + bs[p]];   // (v01, v11)

            float top = (1.0f - wx) * a.x + wx * c.x;
            float bot = (1.0f - wx) * a.y + wx * c.y;
            r[p] = ((1.0f - wy) * top + wy * bot) * (1.0f / 255.0f);
        }
        out[g] = make_float4(r[0], r[1], r[2], r[3]);
    }
}

// ---------------------------------------------------------------------------
// Tail: y is int32; numeric float32 conversion into output tail.
// ---------------------------------------------------------------------------
__global__ void k_tail(const int* __restrict__ y, float* __restrict__ dst, int n)
{
    int i = threadIdx.x;
    if (i < n) dst[i] = (float)y[i];
}

extern "C" void kernel_launch(void* const* d_in, const int* in_sizes, int n_in,
                              void* d_out, int out_size)
{
    const float* x   = (const float*)d_in[0];
    float*       out = (float*)d_out;

    k_reduce  <<<RED_B, 256>>>((const float4*)x);
    k_finalize<<<1, 1024>>>();
    k_hist    <<<TILES, 256>>>(x);
    k_apply   <<<256, 1024>>>((float4*)out);

    int tail = out_size - N_PIX;
    if (tail > 0 && n_in >= 2) {
        k_tail<<<1, 128>>>((const int*)d_in[1], out + N_PIX, tail);
    }
}

// round 5
// speedup vs baseline: 1.1912x; 1.1633x over previous
#include <cuda_runtime.h>
#include <cstdint>
#include <cfloat>

// Problem constants
#define N_PIX   16777216          // 16 * 1 * 1024 * 1024
#define NF4     4194304           // N_PIX / 4
#define RED_B   1024              // reduction blocks
#define BINS    256
#define TILES   1024              // 16 images * 8 * 8
#define CLIPV   2560.0f           // max(int(40.0*16384//256),1)

// Scratch (device globals only — no allocations allowed)
__device__ float         g_pmin[RED_B];
__device__ float         g_pmax[RED_B];
__device__ double        g_psum[RED_B];
__device__ double        g_psq [RED_B];
__device__ float         g_AB[2];
__device__ unsigned char g_bidx[N_PIX];
__device__ unsigned char g_lut8[TILES * BINS];   // LUT values are exact ints 0..255

// ---------------------------------------------------------------------------
// Kernel 1: partial min/max/sum/sumsq. 1024 blocks x 256 threads, 64 elems/thr.
// ---------------------------------------------------------------------------
__global__ void __launch_bounds__(256) k_reduce(const float4* __restrict__ x)
{
    int tid = threadIdx.x;
    int t   = blockIdx.x * 256 + tid;

    float mn =  FLT_MAX, mx = -FLT_MAX;
    float s = 0.0f, q = 0.0f;
#pragma unroll
    for (int i = 0; i < 16; i++) {
        float4 v = x[t + i * (RED_B * 256)];
        mn = fminf(mn, fminf(fminf(v.x, v.y), fminf(v.z, v.w)));
        mx = fmaxf(mx, fmaxf(fmaxf(v.x, v.y), fmaxf(v.z, v.w)));
        s += (v.x + v.y) + (v.z + v.w);
        q += (v.x * v.x + v.y * v.y) + (v.z * v.z + v.w * v.w);
    }

    __shared__ float  smn[256], smx[256];
    __shared__ double ss[256], sq[256];
    smn[tid] = mn; smx[tid] = mx;
    ss[tid] = (double)s; sq[tid] = (double)q;
    __syncthreads();
    for (int o = 128; o > 0; o >>= 1) {
        if (tid < o) {
            smn[tid] = fminf(smn[tid], smn[tid + o]);
            smx[tid] = fmaxf(smx[tid], smx[tid + o]);
            ss[tid] += ss[tid + o];
            sq[tid] += sq[tid + o];
        }
        __syncthreads();
    }
    if (tid == 0) {
        g_pmin[blockIdx.x] = smn[0];
        g_pmax[blockIdx.x] = smx[0];
        g_psum[blockIdx.x] = ss[0];
        g_psq [blockIdx.x] = sq[0];
    }
}

// ---------------------------------------------------------------------------
// Kernel 2: final reduce + affine constants (fp64 replica of the reference's
// normalize -> standardize -> normalize chain, collapsed to x*A+B)
// ---------------------------------------------------------------------------
__global__ void __launch_bounds__(1024) k_finalize()
{
    int tid = threadIdx.x;
    __shared__ float  smn[1024], smx[1024];
    __shared__ double ss[1024], sq[1024];
    smn[tid] = g_pmin[tid]; smx[tid] = g_pmax[tid];
    ss[tid]  = g_psum[tid]; sq[tid]  = g_psq[tid];
    __syncthreads();
    for (int o = 512; o > 0; o >>= 1) {
        if (tid < o) {
            smn[tid] = fminf(smn[tid], smn[tid + o]);
            smx[tid] = fmaxf(smx[tid], smx[tid + o]);
            ss[tid] += ss[tid + o];
            sq[tid] += sq[tid + o];
        }
        __syncthreads();
    }
    if (tid == 0) {
        double mn = (double)smn[0];
        double mx = (double)smx[0];
        double span = mx - mn;
        const double N = (double)N_PIX;
        double S = ss[0], Q = sq[0];
        double meanx = S / N;
        double varx  = (Q - S * S / N) / (N - 1.0);
        double mean1 = (meanx - mn) / span;
        double std1  = sqrt(varx) / span;
        double zmin  = (0.0 - mean1) / std1;
        double zmax  = (1.0 - mean1) / std1;
        double zspan = zmax - zmin;
        double A = 1.0 / (span * std1 * zspan);
        double B = (((0.0 - mn) / span - mean1) / std1 - zmin) / zspan;
        g_AB[0] = (float)A;
        g_AB[1] = (float)B;
    }
}

// ---------------------------------------------------------------------------
// Kernel 3: one block per 128x128 tile. Histogram with 8 per-warp
// sub-histograms + bidx store, then clip -> scan -> residual -> LUT in-block.
// ---------------------------------------------------------------------------
__global__ void __launch_bounds__(256) k_hist(const float* __restrict__ x)
{
    __shared__ unsigned int h[8][BINS];
    __shared__ float        cs[BINS];

    int t   = blockIdx.x;          // tile id: ((bc*8)+ti)*8+tj
    int tid = threadIdx.x;
#pragma unroll
    for (int k = 0; k < 8; k++) h[k][tid] = 0;
    __syncthreads();

    float A = g_AB[0], B = g_AB[1];

    int bc = t >> 6;
    int ti = (t >> 3) & 7;
    int tj = t & 7;
    int row0 = ti * 128;
    int col0 = tj * 128;
    int wsub = tid >> 5;           // warp-private sub-histogram

    const float4* xp = (const float4*)(x + ((size_t)bc << 20));
    uchar4*       bp = (uchar4*)(g_bidx + ((size_t)bc << 20));

#pragma unroll
    for (int it = 0; it < 16; it++) {
        int row   = row0 + it * 8 + (tid >> 5);
        int cidx4 = (row << 8) + (col0 >> 2) + (tid & 31);  // float4 index
        float4 v  = xp[cidx4];
        int b0 = min(max((int)(fmaf(v.x, A, B) * 256.0f), 0), 255);
        int b1 = min(max((int)(fmaf(v.y, A, B) * 256.0f), 0), 255);
        int b2 = min(max((int)(fmaf(v.z, A, B) * 256.0f), 0), 255);
        int b3 = min(max((int)(fmaf(v.w, A, B) * 256.0f), 0), 255);
        atomicAdd(&h[wsub][b0], 1u);
        atomicAdd(&h[wsub][b1], 1u);
        atomicAdd(&h[wsub][b2], 1u);
        atomicAdd(&h[wsub][b3], 1u);
        bp[cidx4] = make_uchar4((unsigned char)b0, (unsigned char)b1,
                                (unsigned char)b2, (unsigned char)b3);
    }
    __syncthreads();

    unsigned int hv = 0;
#pragma unroll
    for (int k = 0; k < 8; k++) hv += h[k][tid];

    // clip + inclusive scan (Hillis-Steele) over 256 bins
    float v = fminf((float)hv, CLIPV);
    cs[tid] = v;
    __syncthreads();
#pragma unroll
    for (int off = 1; off < BINS; off <<= 1) {
        float add = (tid >= off) ? cs[tid - off] : 0.0f;
        __syncthreads();
        cs[tid] += add;
        __syncthreads();
    }
    float total = cs[BINS - 1];
    float resid = (16384.0f - total) * (1.0f / 256.0f);
    float lv = (cs[tid] + (float)(tid + 1) * resid) * (255.0f / 16384.0f);
    lv = floorf(fminf(fmaxf(lv, 0.0f), 255.0f));
    g_lut8[t * BINS + tid] = (unsigned char)lv;
}

// ---------------------------------------------------------------------------
// Kernel 4: bilinear LUT apply — ONE LDS.32 per pixel.
// Within a 64-row band i0/i1 are constant; table slut[(j0,bin)] packs all four
// corners uchar4(v00, v10, v01, v11) with j1 = min(j0+1,7) folded in. Grid:
// 1024 blocks (image, band, quarter-band) x 256 threads; each iteration is one
// full image row -> wx/j0 are per-thread loop-invariant, wy uniform per iter.
// ---------------------------------------------------------------------------
__device__ __forceinline__ float u8f(unsigned int packed, int sel)
{
    // byte -> float via exponent-bias trick: 0x4B0000vv = 8388608 + vv
    return __int_as_float(__byte_perm(packed, 0x4B000000, sel)) - 8388608.0f;
}

__global__ void __launch_bounds__(256) k_apply(float4* __restrict__ out)
{
    __shared__ unsigned int slut[8 * BINS];   // 8 KB

    int blk  = blockIdx.x;          // 0..1023
    int bc   = blk >> 6;            // image
    int band = (blk >> 2) & 15;     // 64-row band
    int sub  = blk & 3;             // 16-row quarter of band
    int i0   = (band == 0) ? 0 : ((band - 1) >> 1);
    int i1   = min(i0 + 1, 7);

    const unsigned char* lb = g_lut8 + ((size_t)bc << 6) * BINS;
#pragma unroll
    for (int s = threadIdx.x; s < 8 * BINS; s += 256) {
        int j0 = s >> 8, b = s & 255;
        int j1 = min(j0 + 1, 7);
        unsigned int v00 = lb[(((i0 << 3) + j0) << 8) + b];
        unsigned int v10 = lb[(((i1 << 3) + j0) << 8) + b];
        unsigned int v01 = lb[(((i0 << 3) + j1) << 8) + b];
        unsigned int v11 = lb[(((i1 << 3) + j1) << 8) + b];
        slut[s] = v00 | (v10 << 8) | (v01 << 16) | (v11 << 24);
    }
    __syncthreads();

    int tid = threadIdx.x;          // == col4 (float4 column), each it = 1 row

    // per-thread loop-invariant x-interpolation setup (4 pixels)
    float wx[4];
    int   jb[4];                    // (j0 << 8), ready to add bin
#pragma unroll
    for (int p = 0; p < 4; p++) {
        int   col = (tid << 2) + p;
        float gj  = fminf(fmaxf((col + 0.5f) * (1.0f / 128.0f) - 0.5f, 0.0f), 7.0f);
        int   j0  = (int)gj;
        wx[p] = gj - (float)j0;
        jb[p] = j0 << 8;
    }

    int row_base = (band << 6) + (sub << 4);                // first row
    int f4_base  = (bc << 18) + (row_base << 8) + tid;      // float4 index
    const uchar4* bp = (const uchar4*)g_bidx;

#pragma unroll
    for (int it = 0; it < 16; it++) {
        int   row = row_base + it;
        float gi  = fminf(fmaxf((row + 0.5f) * (1.0f / 128.0f) - 0.5f, 0.0f), 7.0f);
        float wy  = gi - (float)i0;

        int g = f4_base + (it << 8);
        uchar4 b4 = bp[g];
        unsigned int bs[4] = { b4.x, b4.y, b4.z, b4.w };

        float r[4];
#pragma unroll
        for (int p = 0; p < 4; p++) {
            unsigned int packed = slut[jb[p] + bs[p]];
            float v00 = u8f(packed, 0x7440);
            float v10 = u8f(packed, 0x7441);
            float v01 = u8f(packed, 0x7442);
            float v11 = u8f(packed, 0x7443);
            float top = fmaf(wx[p], v01 - v00, v00);
            float bot = fmaf(wx[p], v11 - v10, v10);
            r[p] = fmaf(wy, bot - top, top) * (1.0f / 255.0f);
        }
        out[g] = make_float4(r[0], r[1], r[2], r[3]);
    }
}

// ---------------------------------------------------------------------------
// Tail: y is int32; numeric float32 conversion into output tail.
// ---------------------------------------------------------------------------
__global__ void k_tail(const int* __restrict__ y, float* __restrict__ dst, int n)
{
    int i = threadIdx.x;
    if (i < n) dst[i] = (float)y[i];
}

extern "C" void kernel_launch(void* const* d_in, const int* in_sizes, int n_in,
                              void* d_out, int out_size)
{
    const float* x   = (const float*)d_in[0];
    float*       out = (float*)d_out;

    k_reduce  <<<RED_B, 256>>>((const float4*)x);
    k_finalize<<<1, 1024>>>();
    k_hist    <<<TILES, 256>>>(x);
    k_apply   <<<1024, 256>>>((float4*)out);

    int tail = out_size - N_PIX;
    if (tail > 0 && n_in >= 2) {
        k_tail<<<1, 128>>>((const int*)d_in[1], out + N_PIX, tail);
    }
}